// round 2
// baseline (speedup 1.0000x reference)
#include <cuda_runtime.h>
#include <math.h>

#define NMAX 20480
#define KNN  16
#define HDIM 256
#define KT   512

// ---------------- scratch (no allocations allowed) ----------------
__device__ float4 g_c4[NMAX];
__device__ int    g_idx[NMAX * KNN];
__device__ int    g_deg[NMAX];
__device__ float  g_srcnorm[NMAX];
__device__ float  g_bufA[NMAX * HDIM];
__device__ float  g_bufB[NMAX * HDIM];
__device__ float  g_bufC[NMAX * HDIM];

__device__ __forceinline__ float* bufptr(int s) {
    return s == 0 ? g_bufA : (s == 1 ? g_bufB : g_bufC);
}

// ---------------- pack centers into float4 (x,y,z,|c|^2), zero degrees ----------------
__global__ void pack_kernel(const float* __restrict__ centers, int N) {
    int i = blockIdx.x * blockDim.x + threadIdx.x;
    if (i < N) {
        float x = centers[3 * i + 0];
        float y = centers[3 * i + 1];
        float z = centers[3 * i + 2];
        g_c4[i] = make_float4(x, y, z, x * x + y * y + z * z);
        g_deg[i] = 0;
    }
}

// ---------------- brute-force kNN: one thread per query, tiled candidates ----------------
// d2'(i,j) = |c_j|^2 - 2 c_i . c_j   (same ordering as |c_i - c_j|^2)
__global__ void knn_kernel(int N) {
    __shared__ float4 sc[KT];
    int q = blockIdx.x * blockDim.x + threadIdx.x;
    bool valid = (q < N);
    float nx = 0.f, ny = 0.f, nz = 0.f;
    if (valid) {
        float4 p = g_c4[q];
        nx = -2.f * p.x; ny = -2.f * p.y; nz = -2.f * p.z;
    }
    float bd[KNN];
    int   bi[KNN];
#pragma unroll
    for (int k = 0; k < KNN; k++) { bd[k] = 3.4e38f; bi[k] = 0; }

    for (int base = 0; base < N; base += KT) {
        int cnt = min(KT, N - base);
        __syncthreads();
        for (int t = threadIdx.x; t < cnt; t += blockDim.x) sc[t] = g_c4[base + t];
        __syncthreads();
        if (valid) {
#pragma unroll 4
            for (int t = 0; t < cnt; t++) {
                float4 v = sc[t];
                float d = fmaf(v.x, nx, fmaf(v.y, ny, fmaf(v.z, nz, v.w)));
                if (d < bd[KNN - 1]) {
                    bd[KNN - 1] = d; bi[KNN - 1] = base + t;
#pragma unroll
                    for (int k = KNN - 1; k > 0; --k) {
                        if (bd[k] < bd[k - 1]) {
                            float td = bd[k]; bd[k] = bd[k - 1]; bd[k - 1] = td;
                            int   ti = bi[k]; bi[k] = bi[k - 1]; bi[k - 1] = ti;
                        }
                    }
                }
            }
        }
    }
    if (valid) {
#pragma unroll
        for (int k = 0; k < KNN; k++) {
            g_idx[q * KNN + k] = bi[k];
            atomicAdd(&g_deg[bi[k]], 1);
        }
    }
}

// ---------------- src_norm = rsqrt(max(out_deg,1)) ----------------
__global__ void norm_kernel(int N) {
    int i = blockIdx.x * blockDim.x + threadIdx.x;
    if (i < N) {
        float d = (float)g_deg[i];
        g_srcnorm[i] = rsqrtf(fmaxf(d, 1.f));
    }
}

// ---------------- neighbor aggregation: agg[i] = 0.25 * sum_k srcnorm[j]*h[j] ----------------
__global__ void agg_kernel(const float* __restrict__ xin, int srcSel, int dstSel,
                           int F, int N) {
    const float* src = (srcSel < 0) ? xin : bufptr(srcSel);
    float* dst = bufptr(dstSel);
    int tpr = F >> 2;                 // float4 lanes per row (32 or 64)
    int rpb = blockDim.x / tpr;       // rows per block
    int r = threadIdx.x / tpr;
    int c = threadIdx.x % tpr;
    int node = blockIdx.x * rpb + r;
    if (node >= N) return;
    const float4* s4 = (const float4*)src;
    float4 acc = make_float4(0.f, 0.f, 0.f, 0.f);
    const int* ip = &g_idx[node * KNN];
#pragma unroll
    for (int k = 0; k < KNN; k++) {
        int j = __ldg(&ip[k]);
        float s = __ldg(&g_srcnorm[j]);
        float4 v = s4[j * tpr + c];
        acc.x = fmaf(s, v.x, acc.x);
        acc.y = fmaf(s, v.y, acc.y);
        acc.z = fmaf(s, v.z, acc.z);
        acc.w = fmaf(s, v.w, acc.w);
    }
    const float dn = 0.25f;           // 1/sqrt(16)
    ((float4*)dst)[node * tpr + c] =
        make_float4(acc.x * dn, acc.y * dn, acc.z * dn, acc.w * dn);
}

// ---------------- fp32 tiled GEMM + bias + relu : C[M,256] = relu(A[M,K] @ W[K,256] + b) ----------------
// BM=128, BN=64, BK=16, 256 threads, 8x4 micro-tile
__global__ void gemm_kernel(int srcSel, const float* __restrict__ W,
                            const float* __restrict__ bias, int dstSel,
                            int M, int Kd) {
    const float* A = bufptr(srcSel);
    float* C = bufptr(dstSel);
    __shared__ float As[16][132];     // [k][row], padded (132*4=528B, 16B-aligned rows)
    __shared__ float Bs[16][64];      // [k][col]
    int tid = threadIdx.x;
    int tx = tid & 15;                // 0..15 -> 4 cols each
    int ty = tid >> 4;                // 0..15 -> 8 rows each
    int bm0 = blockIdx.x * 128;
    int bn0 = blockIdx.y * 64;

    float acc[8][4];
#pragma unroll
    for (int i = 0; i < 8; i++)
#pragma unroll
        for (int j = 0; j < 4; j++) acc[i][j] = 0.f;

    int ktiles = Kd >> 4;
    for (int kt = 0; kt < ktiles; kt++) {
        // load A tile: 128 rows x 16 k, 2 float4 per thread, transposed store
#pragma unroll
        for (int l = 0; l < 2; l++) {
            int lin = tid + l * 256;
            int arow = lin >> 2;
            int kq = (lin & 3) << 2;
            int grow = bm0 + arow;
            float4 v = make_float4(0.f, 0.f, 0.f, 0.f);
            if (grow < M) v = *(const float4*)&A[grow * Kd + kt * 16 + kq];
            As[kq + 0][arow] = v.x;
            As[kq + 1][arow] = v.y;
            As[kq + 2][arow] = v.z;
            As[kq + 3][arow] = v.w;
        }
        // load B tile: 16 k x 64 cols, 1 float4 per thread
        {
            int brow = tid >> 4;
            int bc = (tid & 15) << 2;
            float4 v = *(const float4*)&W[(kt * 16 + brow) * HDIM + bn0 + bc];
            *(float4*)&Bs[brow][bc] = v;
        }
        __syncthreads();
#pragma unroll
        for (int kk = 0; kk < 16; kk++) {
            float4 a0 = *(const float4*)&As[kk][ty * 8];
            float4 a1 = *(const float4*)&As[kk][ty * 8 + 4];
            float4 b  = *(const float4*)&Bs[kk][tx * 4];
            float a[8] = {a0.x, a0.y, a0.z, a0.w, a1.x, a1.y, a1.z, a1.w};
            float bb[4] = {b.x, b.y, b.z, b.w};
#pragma unroll
            for (int i = 0; i < 8; i++)
#pragma unroll
                for (int j = 0; j < 4; j++)
                    acc[i][j] = fmaf(a[i], bb[j], acc[i][j]);
        }
        __syncthreads();
    }

    float bb[4];
#pragma unroll
    for (int j = 0; j < 4; j++) bb[j] = __ldg(&bias[bn0 + tx * 4 + j]);
#pragma unroll
    for (int i = 0; i < 8; i++) {
        int row = bm0 + ty * 8 + i;
        if (row < M) {
#pragma unroll
            for (int j = 0; j < 4; j++) {
                float v = acc[i][j] + bb[j];
                C[row * HDIM + bn0 + tx * 4 + j] = fmaxf(v, 0.f);
            }
        }
    }
}

// ---------------- final: sigmoid(h @ Wf + bf), one warp per row ----------------
__global__ void final_kernel(int srcSel, const float* __restrict__ Wf,
                             const float* __restrict__ bf,
                             float* __restrict__ out, int N) {
    __shared__ float sw[HDIM];
    const float* h = bufptr(srcSel);
    for (int i = threadIdx.x; i < HDIM; i += blockDim.x) sw[i] = Wf[i];
    __syncthreads();
    int warp = threadIdx.x >> 5;
    int lane = threadIdx.x & 31;
    int row = blockIdx.x * 8 + warp;
    if (row >= N) return;
    const float4* h4 = (const float4*)&h[row * HDIM];
    float4 v0 = h4[lane * 2 + 0];
    float4 v1 = h4[lane * 2 + 1];
    float4 w0 = *(const float4*)&sw[lane * 8 + 0];
    float4 w1 = *(const float4*)&sw[lane * 8 + 4];
    float s = v0.x * w0.x + v0.y * w0.y + v0.z * w0.z + v0.w * w0.w
            + v1.x * w1.x + v1.y * w1.y + v1.z * w1.z + v1.w * w1.w;
#pragma unroll
    for (int o = 16; o > 0; o >>= 1) s += __shfl_xor_sync(0xffffffffu, s, o);
    if (lane == 0) {
        float z = s + bf[0];
        out[row] = 1.f / (1.f + expf(-z));
    }
}

// ---------------- launch ----------------
extern "C" void kernel_launch(void* const* d_in, const int* in_sizes, int n_in,
                              void* d_out, int out_size) {
    const float* x       = (const float*)d_in[0];
    const float* centers = (const float*)d_in[1];
    const float* W0      = (const float*)d_in[2];
    const float* b0      = (const float*)d_in[3];
    const float* W1      = (const float*)d_in[4];
    const float* b1      = (const float*)d_in[5];
    const float* W2      = (const float*)d_in[6];
    const float* b2      = (const float*)d_in[7];
    const float* Wf      = (const float*)d_in[8];
    const float* bf      = (const float*)d_in[9];
    float* out = (float*)d_out;

    int N = in_sizes[1] / 3;           // 20000
    int D = in_sizes[0] / N;           // 128

    pack_kernel<<<(N + 255) / 256, 256>>>(centers, N);
    knn_kernel<<<(N + 127) / 128, 128>>>(N);
    norm_kernel<<<(N + 255) / 256, 256>>>(N);

    dim3 gg((N + 127) / 128, HDIM / 64);

    // layer 0: agg(x) [N,D] -> bufA ; gemm K=D -> bufB
    {
        int tpr = D / 4, rpb = 256 / tpr;
        agg_kernel<<<(N + rpb - 1) / rpb, 256>>>(x, -1, 0, D, N);
    }
    gemm_kernel<<<gg, 256>>>(0, W0, b0, 1, N, D);

    // layer 1: agg(bufB) -> bufA ; gemm -> bufC
    {
        int tpr = HDIM / 4, rpb = 256 / tpr;
        agg_kernel<<<(N + rpb - 1) / rpb, 256>>>(nullptr, 1, 0, HDIM, N);
    }
    gemm_kernel<<<gg, 256>>>(0, W1, b1, 2, N, HDIM);

    // layer 2: agg(bufC) -> bufA ; gemm -> bufB
    {
        int tpr = HDIM / 4, rpb = 256 / tpr;
        agg_kernel<<<(N + rpb - 1) / rpb, 256>>>(nullptr, 2, 0, HDIM, N);
    }
    gemm_kernel<<<gg, 256>>>(0, W2, b2, 1, N, HDIM);

    final_kernel<<<(N + 7) / 8, 256>>>(1, Wf, bf, out, N);
}

// round 3
// speedup vs baseline: 1.2744x; 1.2744x over previous
#include <cuda_runtime.h>
#include <math.h>

#define NMAX 20480
#define KNN  16
#define HDIM 256
#define KT   1024
#define CSPLIT 2

// ---------------- scratch (no allocations allowed) ----------------
__device__ float4 g_c4[NMAX];
__device__ int    g_idx[NMAX * KNN];
__device__ int    g_deg[NMAX];
__device__ float  g_srcnorm[NMAX];
__device__ float  g_pd[CSPLIT * NMAX * KNN];   // partial top-16 distances (sorted asc)
__device__ int    g_pi[CSPLIT * NMAX * KNN];   // partial top-16 indices
__device__ float  g_bufA[NMAX * HDIM];
__device__ float  g_bufB[NMAX * HDIM];
__device__ float  g_bufC[NMAX * HDIM];

__device__ __forceinline__ float* bufptr(int s) {
    return s == 0 ? g_bufA : (s == 1 ? g_bufB : g_bufC);
}

// ---------------- pack centers into float4 (x,y,z,|c|^2), zero degrees ----------------
__global__ void pack_kernel(const float* __restrict__ centers, int N) {
    int i = blockIdx.x * blockDim.x + threadIdx.x;
    if (i < N) {
        float x = centers[3 * i + 0];
        float y = centers[3 * i + 1];
        float z = centers[3 * i + 2];
        g_c4[i] = make_float4(x, y, z, x * x + y * y + z * z);
        g_deg[i] = 0;
    }
}

// ---------------- brute-force kNN partial: thread-per-query, candidate chunk per blockIdx.y --------
// d'(i,j) = |c_j|^2 - 2 c_i . c_j  (same ordering as |c_i - c_j|^2)
__global__ void knn_part_kernel(int N) {
    __shared__ float4 sc[KT];
    int q = blockIdx.x * blockDim.x + threadIdx.x;
    int chunk = (N + CSPLIT - 1) / CSPLIT;
    int c0 = blockIdx.y * chunk;
    int c1 = min(N, c0 + chunk);
    bool valid = (q < N);

    float nx = 0.f, ny = 0.f, nz = 0.f;
    if (valid) {
        float4 p = g_c4[q];
        nx = -2.f * p.x; ny = -2.f * p.y; nz = -2.f * p.z;
    }
    float bd[KNN];
    int   bi[KNN];
#pragma unroll
    for (int k = 0; k < KNN; k++) { bd[k] = 3.4e38f; bi[k] = 0; }

    for (int base = c0; base < c1; base += KT) {
        int cnt = min(KT, c1 - base);
        __syncthreads();
        for (int t = threadIdx.x; t < cnt; t += blockDim.x) sc[t] = g_c4[base + t];
        __syncthreads();
        if (valid) {
#pragma unroll 4
            for (int t = 0; t < cnt; t++) {
                float4 v = sc[t];
                float d = fmaf(v.x, nx, fmaf(v.y, ny, fmaf(v.z, nz, v.w)));
                if (d < bd[KNN - 1]) {
                    // predicated shift-insert into ascending sorted list
                    float cd = d; int ci = base + t;
#pragma unroll
                    for (int k = 0; k < KNN; k++) {
                        bool lt = cd < bd[k];
                        float lo = fminf(cd, bd[k]);
                        float hi = fmaxf(cd, bd[k]);
                        int ni = lt ? ci : bi[k];
                        ci = lt ? bi[k] : ci;
                        bd[k] = lo; bi[k] = ni; cd = hi;
                    }
                }
            }
        }
    }
    if (valid) {
        int o = (blockIdx.y * N + q) * KNN;
#pragma unroll
        for (int k = 0; k < KNN; k++) {
            g_pd[o + k] = bd[k];
            g_pi[o + k] = bi[k];
        }
    }
}

// ---------------- merge CSPLIT sorted 16-lists -> final top-16, accumulate out-degree ------------
__global__ void knn_merge_kernel(int N) {
    int q = blockIdx.x * blockDim.x + threadIdx.x;
    if (q >= N) return;
    const float* A = &g_pd[(0 * N + q) * KNN];
    const float* B = &g_pd[(1 * N + q) * KNN];
    const int*   IA = &g_pi[(0 * N + q) * KNN];
    const int*   IB = &g_pi[(1 * N + q) * KNN];
    int pa = 0, pb = 0;
#pragma unroll
    for (int k = 0; k < KNN; k++) {
        float va = __ldg(&A[pa]);
        float vb = __ldg(&B[pb]);
        int j;
        if (va <= vb) { j = __ldg(&IA[pa]); pa++; }
        else          { j = __ldg(&IB[pb]); pb++; }
        g_idx[q * KNN + k] = j;
        atomicAdd(&g_deg[j], 1);
    }
}

// ---------------- src_norm = rsqrt(max(out_deg,1)) ----------------
__global__ void norm_kernel(int N) {
    int i = blockIdx.x * blockDim.x + threadIdx.x;
    if (i < N) {
        float d = (float)g_deg[i];
        g_srcnorm[i] = rsqrtf(fmaxf(d, 1.f));
    }
}

// ---------------- neighbor aggregation: agg[i] = 0.25 * sum_k srcnorm[j]*h[j] ----------------
__global__ void agg_kernel(const float* __restrict__ xin, int srcSel, int dstSel,
                           int F, int N) {
    const float* src = (srcSel < 0) ? xin : bufptr(srcSel);
    float* dst = bufptr(dstSel);
    int tpr = F >> 2;                 // float4 lanes per row (32 or 64)
    int rpb = blockDim.x / tpr;       // rows per block
    int r = threadIdx.x / tpr;
    int c = threadIdx.x % tpr;
    int node = blockIdx.x * rpb + r;
    if (node >= N) return;
    const float4* s4 = (const float4*)src;
    float4 acc = make_float4(0.f, 0.f, 0.f, 0.f);
    const int* ip = &g_idx[node * KNN];
#pragma unroll
    for (int k = 0; k < KNN; k++) {
        int j = __ldg(&ip[k]);
        float s = __ldg(&g_srcnorm[j]);
        float4 v = s4[j * tpr + c];
        acc.x = fmaf(s, v.x, acc.x);
        acc.y = fmaf(s, v.y, acc.y);
        acc.z = fmaf(s, v.z, acc.z);
        acc.w = fmaf(s, v.w, acc.w);
    }
    const float dn = 0.25f;           // 1/sqrt(16)
    ((float4*)dst)[node * tpr + c] =
        make_float4(acc.x * dn, acc.y * dn, acc.z * dn, acc.w * dn);
}

// ---------------- fp32 tiled GEMM + bias + relu : C[M,256] = relu(A[M,K] @ W[K,256] + b) ----------
// BM=128, BN=128, BK=16, 256 threads, 8x8 micro-tile
__global__ void gemm_kernel(int srcSel, const float* __restrict__ W,
                            const float* __restrict__ bias, int dstSel,
                            int M, int Kd) {
    const float* A = bufptr(srcSel);
    float* C = bufptr(dstSel);
    __shared__ float As[16][132];     // [k][row], padded
    __shared__ float Bs[16][128];     // [k][col]
    int tid = threadIdx.x;
    int tx = tid & 15;                // 0..15 -> 8 cols each
    int ty = tid >> 4;                // 0..15 -> 8 rows each
    int bm0 = blockIdx.x * 128;
    int bn0 = blockIdx.y * 128;

    float acc[8][8];
#pragma unroll
    for (int i = 0; i < 8; i++)
#pragma unroll
        for (int j = 0; j < 8; j++) acc[i][j] = 0.f;

    int ktiles = Kd >> 4;
    for (int kt = 0; kt < ktiles; kt++) {
        // load A tile: 128 rows x 16 k, 2 float4 per thread, transposed store
#pragma unroll
        for (int l = 0; l < 2; l++) {
            int lin = tid + l * 256;
            int arow = lin >> 2;
            int kq = (lin & 3) << 2;
            int grow = bm0 + arow;
            float4 v = make_float4(0.f, 0.f, 0.f, 0.f);
            if (grow < M) v = *(const float4*)&A[grow * Kd + kt * 16 + kq];
            As[kq + 0][arow] = v.x;
            As[kq + 1][arow] = v.y;
            As[kq + 2][arow] = v.z;
            As[kq + 3][arow] = v.w;
        }
        // load B tile: 16 k x 128 cols, 2 float4 per thread
#pragma unroll
        for (int l = 0; l < 2; l++) {
            int lin = tid + l * 256;
            int brow = lin >> 5;
            int bc = (lin & 31) << 2;
            float4 v = *(const float4*)&W[(kt * 16 + brow) * HDIM + bn0 + bc];
            *(float4*)&Bs[brow][bc] = v;
        }
        __syncthreads();
#pragma unroll
        for (int kk = 0; kk < 16; kk++) {
            float4 a0 = *(const float4*)&As[kk][ty * 8];
            float4 a1 = *(const float4*)&As[kk][ty * 8 + 4];
            float4 b0 = *(const float4*)&Bs[kk][tx * 8];
            float4 b1 = *(const float4*)&Bs[kk][tx * 8 + 4];
            float a[8] = {a0.x, a0.y, a0.z, a0.w, a1.x, a1.y, a1.z, a1.w};
            float bb[8] = {b0.x, b0.y, b0.z, b0.w, b1.x, b1.y, b1.z, b1.w};
#pragma unroll
            for (int i = 0; i < 8; i++)
#pragma unroll
                for (int j = 0; j < 8; j++)
                    acc[i][j] = fmaf(a[i], bb[j], acc[i][j]);
        }
        __syncthreads();
    }

    float bb[8];
#pragma unroll
    for (int j = 0; j < 8; j++) bb[j] = __ldg(&bias[bn0 + tx * 8 + j]);
#pragma unroll
    for (int i = 0; i < 8; i++) {
        int row = bm0 + ty * 8 + i;
        if (row < M) {
            float4 o0, o1;
            o0.x = fmaxf(acc[i][0] + bb[0], 0.f);
            o0.y = fmaxf(acc[i][1] + bb[1], 0.f);
            o0.z = fmaxf(acc[i][2] + bb[2], 0.f);
            o0.w = fmaxf(acc[i][3] + bb[3], 0.f);
            o1.x = fmaxf(acc[i][4] + bb[4], 0.f);
            o1.y = fmaxf(acc[i][5] + bb[5], 0.f);
            o1.z = fmaxf(acc[i][6] + bb[6], 0.f);
            o1.w = fmaxf(acc[i][7] + bb[7], 0.f);
            *(float4*)&C[row * HDIM + bn0 + tx * 8 + 0] = o0;
            *(float4*)&C[row * HDIM + bn0 + tx * 8 + 4] = o1;
        }
    }
}

// ---------------- final: sigmoid(h @ Wf + bf), one warp per row ----------------
__global__ void final_kernel(int srcSel, const float* __restrict__ Wf,
                             const float* __restrict__ bf,
                             float* __restrict__ out, int N) {
    __shared__ float sw[HDIM];
    const float* h = bufptr(srcSel);
    for (int i = threadIdx.x; i < HDIM; i += blockDim.x) sw[i] = Wf[i];
    __syncthreads();
    int warp = threadIdx.x >> 5;
    int lane = threadIdx.x & 31;
    int row = blockIdx.x * 8 + warp;
    if (row >= N) return;
    const float4* h4 = (const float4*)&h[row * HDIM];
    float4 v0 = h4[lane * 2 + 0];
    float4 v1 = h4[lane * 2 + 1];
    float4 w0 = *(const float4*)&sw[lane * 8 + 0];
    float4 w1 = *(const float4*)&sw[lane * 8 + 4];
    float s = v0.x * w0.x + v0.y * w0.y + v0.z * w0.z + v0.w * w0.w
            + v1.x * w1.x + v1.y * w1.y + v1.z * w1.z + v1.w * w1.w;
#pragma unroll
    for (int o = 16; o > 0; o >>= 1) s += __shfl_xor_sync(0xffffffffu, s, o);
    if (lane == 0) {
        float z = s + bf[0];
        out[row] = 1.f / (1.f + expf(-z));
    }
}

// ---------------- launch ----------------
extern "C" void kernel_launch(void* const* d_in, const int* in_sizes, int n_in,
                              void* d_out, int out_size) {
    const float* x       = (const float*)d_in[0];
    const float* centers = (const float*)d_in[1];
    const float* W0      = (const float*)d_in[2];
    const float* b0      = (const float*)d_in[3];
    const float* W1      = (const float*)d_in[4];
    const float* b1      = (const float*)d_in[5];
    const float* W2      = (const float*)d_in[6];
    const float* b2      = (const float*)d_in[7];
    const float* Wf      = (const float*)d_in[8];
    const float* bf      = (const float*)d_in[9];
    float* out = (float*)d_out;

    int N = in_sizes[1] / 3;           // 20000
    int D = in_sizes[0] / N;           // 128

    pack_kernel<<<(N + 255) / 256, 256>>>(centers, N);
    {
        dim3 kg((N + 127) / 128, CSPLIT);
        knn_part_kernel<<<kg, 128>>>(N);
    }
    knn_merge_kernel<<<(N + 127) / 128, 128>>>(N);
    norm_kernel<<<(N + 255) / 256, 256>>>(N);

    dim3 gg((N + 127) / 128, HDIM / 128);

    // layer 0: agg(x) [N,D] -> bufA ; gemm K=D -> bufB
    {
        int tpr = D / 4, rpb = 256 / tpr;
        agg_kernel<<<(N + rpb - 1) / rpb, 256>>>(x, -1, 0, D, N);
    }
    gemm_kernel<<<gg, 256>>>(0, W0, b0, 1, N, D);

    // layer 1: agg(bufB) -> bufA ; gemm -> bufC
    {
        int tpr = HDIM / 4, rpb = 256 / tpr;
        agg_kernel<<<(N + rpb - 1) / rpb, 256>>>(nullptr, 1, 0, HDIM, N);
    }
    gemm_kernel<<<gg, 256>>>(0, W1, b1, 2, N, HDIM);

    // layer 2: agg(bufC) -> bufA ; gemm -> bufB
    {
        int tpr = HDIM / 4, rpb = 256 / tpr;
        agg_kernel<<<(N + rpb - 1) / rpb, 256>>>(nullptr, 2, 0, HDIM, N);
    }
    gemm_kernel<<<gg, 256>>>(0, W2, b2, 1, N, HDIM);

    final_kernel<<<(N + 7) / 8, 256>>>(1, Wf, bf, out, N);
}

// round 5
// speedup vs baseline: 1.3408x; 1.0521x over previous
#include <cuda_runtime.h>
#include <math.h>

#define NMAX   20480
#define KNN    16
#define HDIM   256
#define SAMPLE 2560
#define NSUB   64
#define SUBW   (SAMPLE / NSUB)     // 40
#define KTB    1024
#define CSPB   8                   // phase-B candidate split
#define CAP    512                 // survivor capacity per query

// ---------------- scratch (no allocations allowed) ----------------
__device__ float4 g_c4[NMAX];
__device__ float  g_thr[NMAX];
__device__ int    g_scnt[NMAX];
__device__ int2   g_surv[(size_t)NMAX * CAP];   // (dist bits, idx)
__device__ int    g_idx[NMAX * KNN];
__device__ int    g_deg[NMAX];
__device__ float  g_srcnorm[NMAX];
__device__ float  g_bufA[NMAX * HDIM];
__device__ float  g_bufB[NMAX * HDIM];
__device__ float  g_bufC[NMAX * HDIM];

__device__ __forceinline__ float* bufptr(int s) {
    return s == 0 ? g_bufA : (s == 1 ? g_bufB : g_bufC);
}

// ---------------- pack centers into float4 (x,y,z,|c|^2), zero degrees/counters --------
__global__ void pack_kernel(const float* __restrict__ centers, int N) {
    int i = blockIdx.x * blockDim.x + threadIdx.x;
    if (i < N) {
        float x = centers[3 * i + 0];
        float y = centers[3 * i + 1];
        float z = centers[3 * i + 2];
        g_c4[i] = make_float4(x, y, z, x * x + y * y + z * z);
        g_deg[i] = 0;
        g_scnt[i] = 0;
    }
}

// ---------------- Phase A: divergence-free threshold ----------------
// 64 sub-block minima over a 2560 sample; t = 16th smallest of the 64 minima.
// 64 distinct candidates with d <= their submin <= ... guarantees >=16 elements <= t,
// hence t >= true 16th-NN distance: filter in phase B keeps a superset of top-16.
__global__ void knn_thresh_kernel(int N) {
    __shared__ float4 sc[SAMPLE];
    int q = blockIdx.x * blockDim.x + threadIdx.x;
    for (int t = threadIdx.x; t < SAMPLE; t += blockDim.x)
        sc[t] = g_c4[t < N ? t : (N - 1)];
    __syncthreads();
    if (q >= N) return;
    float4 p = g_c4[q];
    float nx = -2.f * p.x, ny = -2.f * p.y, nz = -2.f * p.z;

    float bd[KNN];
#pragma unroll
    for (int k = 0; k < KNN; k++) bd[k] = 3.4e38f;

    for (int b = 0; b < NSUB; b++) {
        float mm = 3.4e38f;
#pragma unroll 8
        for (int j = 0; j < SUBW; j++) {
            float4 v = sc[b * SUBW + j];
            float d = fmaf(v.x, nx, fmaf(v.y, ny, fmaf(v.z, nz, v.w)));
            mm = fminf(mm, d);
        }
        // value-only sorted-16 insert (min/max chain, branch-free)
        float cd = mm;
#pragma unroll
        for (int k = 0; k < KNN; k++) {
            float lo = fminf(cd, bd[k]);
            float hi = fmaxf(cd, bd[k]);
            bd[k] = lo; cd = hi;
        }
    }
    g_thr[q] = bd[KNN - 1];
}

// ---------------- Phase B: filtered full scan, append survivors ----------------
// QPT=2 queries per thread (halves smem traffic), candidates split 8-way for occupancy.
__global__ void knn_filter_kernel(int N) {
    __shared__ float4 sc[KTB];
    int half = (N + 1) >> 1;
    int t0i = blockIdx.x * blockDim.x + threadIdx.x;
    int q0 = t0i;
    int q1 = t0i + half;
    bool v0 = (q0 < N);
    bool v1 = (q1 < N);

    int chunk = (N + CSPB - 1) / CSPB;
    int c0 = blockIdx.y * chunk;
    int c1 = min(N, c0 + chunk);

    float nx0 = 0.f, ny0 = 0.f, nz0 = 0.f, th0 = -3.4e38f;
    float nx1 = 0.f, ny1 = 0.f, nz1 = 0.f, th1 = -3.4e38f;
    if (v0) {
        float4 p = g_c4[q0];
        nx0 = -2.f * p.x; ny0 = -2.f * p.y; nz0 = -2.f * p.z;
        th0 = g_thr[q0];
    }
    if (v1) {
        float4 p = g_c4[q1];
        nx1 = -2.f * p.x; ny1 = -2.f * p.y; nz1 = -2.f * p.z;
        th1 = g_thr[q1];
    }

    for (int base = c0; base < c1; base += KTB) {
        int cnt = min(KTB, c1 - base);
        __syncthreads();
        for (int t = threadIdx.x; t < cnt; t += blockDim.x) sc[t] = g_c4[base + t];
        __syncthreads();
#pragma unroll 4
        for (int t = 0; t < cnt; t++) {
            float4 v = sc[t];
            float d0 = fmaf(v.x, nx0, fmaf(v.y, ny0, fmaf(v.z, nz0, v.w)));
            float d1 = fmaf(v.x, nx1, fmaf(v.y, ny1, fmaf(v.z, nz1, v.w)));
            if (d0 <= th0) {
                int s = atomicAdd(&g_scnt[q0], 1);
                if (s < CAP) g_surv[(size_t)q0 * CAP + s] =
                    make_int2(__float_as_int(d0), base + t);
            }
            if (d1 <= th1) {
                int s = atomicAdd(&g_scnt[q1], 1);
                if (s < CAP) g_surv[(size_t)q1 * CAP + s] =
                    make_int2(__float_as_int(d1), base + t);
            }
        }
    }
}

// ---------------- Phase C: exact top-16 of survivors + degree accumulation -------------
__global__ void knn_select_kernel(int N) {
    int q = blockIdx.x * blockDim.x + threadIdx.x;
    if (q >= N) return;
    int cnt = min(g_scnt[q], CAP);
    const int2* sv = &g_surv[(size_t)q * CAP];
    float bd[KNN];
    int   bi[KNN];
#pragma unroll
    for (int k = 0; k < KNN; k++) { bd[k] = 3.4e38f; bi[k] = 0; }
    for (int s = 0; s < cnt; s++) {
        int2 e = __ldg(&sv[s]);
        float cd = __int_as_float(e.x);
        if (cd < bd[KNN - 1]) {
            int ci = e.y;
#pragma unroll
            for (int k = 0; k < KNN; k++) {
                bool lt = cd < bd[k];
                float lo = fminf(cd, bd[k]);
                float hi = fmaxf(cd, bd[k]);
                int ni = lt ? ci : bi[k];
                ci = lt ? bi[k] : ci;
                bd[k] = lo; bi[k] = ni; cd = hi;
            }
        }
    }
#pragma unroll
    for (int k = 0; k < KNN; k++) {
        g_idx[q * KNN + k] = bi[k];
        atomicAdd(&g_deg[bi[k]], 1);
    }
}

// ---------------- src_norm = rsqrt(max(out_deg,1)) ----------------
__global__ void norm_kernel(int N) {
    int i = blockIdx.x * blockDim.x + threadIdx.x;
    if (i < N) {
        float d = (float)g_deg[i];
        g_srcnorm[i] = rsqrtf(fmaxf(d, 1.f));
    }
}

// ---------------- neighbor aggregation: agg[i] = 0.25 * sum_k srcnorm[j]*h[j] ----------
__global__ void agg_kernel(const float* __restrict__ xin, int srcSel, int dstSel,
                           int F, int N) {
    const float* src = (srcSel < 0) ? xin : bufptr(srcSel);
    float* dst = bufptr(dstSel);
    int tpr = F >> 2;
    int rpb = blockDim.x / tpr;
    int r = threadIdx.x / tpr;
    int c = threadIdx.x % tpr;
    int node = blockIdx.x * rpb + r;
    if (node >= N) return;
    const float4* s4 = (const float4*)src;
    float4 acc = make_float4(0.f, 0.f, 0.f, 0.f);
    const int* ip = &g_idx[node * KNN];
#pragma unroll
    for (int k = 0; k < KNN; k++) {
        int j = __ldg(&ip[k]);
        float s = __ldg(&g_srcnorm[j]);
        float4 v = s4[j * tpr + c];
        acc.x = fmaf(s, v.x, acc.x);
        acc.y = fmaf(s, v.y, acc.y);
        acc.z = fmaf(s, v.z, acc.z);
        acc.w = fmaf(s, v.w, acc.w);
    }
    const float dn = 0.25f;
    ((float4*)dst)[node * tpr + c] =
        make_float4(acc.x * dn, acc.y * dn, acc.z * dn, acc.w * dn);
}

// ---------------- fp32 tiled GEMM + bias + relu : C = relu(A[M,K] @ W[K,256] + b) ------
// BM=128, BN=128, BK=16, 256 threads, 8x8 micro-tile
__global__ void gemm_kernel(int srcSel, const float* __restrict__ W,
                            const float* __restrict__ bias, int dstSel,
                            int M, int Kd) {
    const float* A = bufptr(srcSel);
    float* C = bufptr(dstSel);
    __shared__ float As[16][132];
    __shared__ float Bs[16][128];
    int tid = threadIdx.x;
    int tx = tid & 15;
    int ty = tid >> 4;
    int bm0 = blockIdx.x * 128;
    int bn0 = blockIdx.y * 128;

    float acc[8][8];
#pragma unroll
    for (int i = 0; i < 8; i++)
#pragma unroll
        for (int j = 0; j < 8; j++) acc[i][j] = 0.f;

    int ktiles = Kd >> 4;
    for (int kt = 0; kt < ktiles; kt++) {
#pragma unroll
        for (int l = 0; l < 2; l++) {
            int lin = tid + l * 256;
            int arow = lin >> 2;
            int kq = (lin & 3) << 2;
            int grow = bm0 + arow;
            float4 v = make_float4(0.f, 0.f, 0.f, 0.f);
            if (grow < M) v = *(const float4*)&A[grow * Kd + kt * 16 + kq];
            As[kq + 0][arow] = v.x;
            As[kq + 1][arow] = v.y;
            As[kq + 2][arow] = v.z;
            As[kq + 3][arow] = v.w;
        }
#pragma unroll
        for (int l = 0; l < 2; l++) {
            int lin = tid + l * 256;
            int brow = lin >> 5;
            int bc = (lin & 31) << 2;
            float4 v = *(const float4*)&W[(kt * 16 + brow) * HDIM + bn0 + bc];
            *(float4*)&Bs[brow][bc] = v;
        }
        __syncthreads();
#pragma unroll
        for (int kk = 0; kk < 16; kk++) {
            float4 a0 = *(const float4*)&As[kk][ty * 8];
            float4 a1 = *(const float4*)&As[kk][ty * 8 + 4];
            float4 b0 = *(const float4*)&Bs[kk][tx * 8];
            float4 b1 = *(const float4*)&Bs[kk][tx * 8 + 4];
            float a[8] = {a0.x, a0.y, a0.z, a0.w, a1.x, a1.y, a1.z, a1.w};
            float bb[8] = {b0.x, b0.y, b0.z, b0.w, b1.x, b1.y, b1.z, b1.w};
#pragma unroll
            for (int i = 0; i < 8; i++)
#pragma unroll
                for (int j = 0; j < 8; j++)
                    acc[i][j] = fmaf(a[i], bb[j], acc[i][j]);
        }
        __syncthreads();
    }

    float bb[8];
#pragma unroll
    for (int j = 0; j < 8; j++) bb[j] = __ldg(&bias[bn0 + tx * 8 + j]);
#pragma unroll
    for (int i = 0; i < 8; i++) {
        int row = bm0 + ty * 8 + i;
        if (row < M) {
            float4 o0, o1;
            o0.x = fmaxf(acc[i][0] + bb[0], 0.f);
            o0.y = fmaxf(acc[i][1] + bb[1], 0.f);
            o0.z = fmaxf(acc[i][2] + bb[2], 0.f);
            o0.w = fmaxf(acc[i][3] + bb[3], 0.f);
            o1.x = fmaxf(acc[i][4] + bb[4], 0.f);
            o1.y = fmaxf(acc[i][5] + bb[5], 0.f);
            o1.z = fmaxf(acc[i][6] + bb[6], 0.f);
            o1.w = fmaxf(acc[i][7] + bb[7], 0.f);
            *(float4*)&C[row * HDIM + bn0 + tx * 8 + 0] = o0;
            *(float4*)&C[row * HDIM + bn0 + tx * 8 + 4] = o1;
        }
    }
}

// ---------------- final: sigmoid(h @ Wf + bf), one warp per row ----------------
__global__ void final_kernel(int srcSel, const float* __restrict__ Wf,
                             const float* __restrict__ bf,
                             float* __restrict__ out, int N) {
    __shared__ float sw[HDIM];
    const float* h = bufptr(srcSel);
    for (int i = threadIdx.x; i < HDIM; i += blockDim.x) sw[i] = Wf[i];
    __syncthreads();
    int warp = threadIdx.x >> 5;
    int lane = threadIdx.x & 31;
    int row = blockIdx.x * 8 + warp;
    if (row >= N) return;
    const float4* h4 = (const float4*)&h[row * HDIM];
    float4 v0 = h4[lane * 2 + 0];
    float4 v1 = h4[lane * 2 + 1];
    float4 w0 = *(const float4*)&sw[lane * 8 + 0];
    float4 w1 = *(const float4*)&sw[lane * 8 + 4];
    float s = v0.x * w0.x + v0.y * w0.y + v0.z * w0.z + v0.w * w0.w
            + v1.x * w1.x + v1.y * w1.y + v1.z * w1.z + v1.w * w1.w;
#pragma unroll
    for (int o = 16; o > 0; o >>= 1) s += __shfl_xor_sync(0xffffffffu, s, o);
    if (lane == 0) {
        float z = s + bf[0];
        out[row] = 1.f / (1.f + expf(-z));
    }
}

// ---------------- launch ----------------
extern "C" void kernel_launch(void* const* d_in, const int* in_sizes, int n_in,
                              void* d_out, int out_size) {
    const float* x       = (const float*)d_in[0];
    const float* centers = (const float*)d_in[1];
    const float* W0      = (const float*)d_in[2];
    const float* b0      = (const float*)d_in[3];
    const float* W1      = (const float*)d_in[4];
    const float* b1      = (const float*)d_in[5];
    const float* W2      = (const float*)d_in[6];
    const float* b2      = (const float*)d_in[7];
    const float* Wf      = (const float*)d_in[8];
    const float* bf      = (const float*)d_in[9];
    float* out = (float*)d_out;

    int N = in_sizes[1] / 3;           // 20000
    int D = in_sizes[0] / N;           // 128

    pack_kernel<<<(N + 255) / 256, 256>>>(centers, N);
    knn_thresh_kernel<<<(N + 127) / 128, 128>>>(N);
    {
        int half = (N + 1) / 2;
        dim3 kg((half + 127) / 128, CSPB);
        knn_filter_kernel<<<kg, 128>>>(N);
    }
    knn_select_kernel<<<(N + 127) / 128, 128>>>(N);
    norm_kernel<<<(N + 255) / 256, 256>>>(N);

    dim3 gg((N + 127) / 128, HDIM / 128);

    {
        int tpr = D / 4, rpb = 256 / tpr;
        agg_kernel<<<(N + rpb - 1) / rpb, 256>>>(x, -1, 0, D, N);
    }
    gemm_kernel<<<gg, 256>>>(0, W0, b0, 1, N, D);

    {
        int tpr = HDIM / 4, rpb = 256 / tpr;
        agg_kernel<<<(N + rpb - 1) / rpb, 256>>>(nullptr, 1, 0, HDIM, N);
    }
    gemm_kernel<<<gg, 256>>>(0, W1, b1, 2, N, HDIM);

    {
        int tpr = HDIM / 4, rpb = 256 / tpr;
        agg_kernel<<<(N + rpb - 1) / rpb, 256>>>(nullptr, 2, 0, HDIM, N);
    }
    gemm_kernel<<<gg, 256>>>(0, W2, b2, 1, N, HDIM);

    final_kernel<<<(N + 7) / 8, 256>>>(1, Wf, bf, out, N);
}

// round 8
// speedup vs baseline: 1.8776x; 1.4004x over previous
#include <cuda_runtime.h>
#include <math.h>

#define NMAX   20480
#define KNN    16
#define HDIM   256
#define SAMPLE 8192
#define SUBW   16
#define THTILE 2048                // smem tile for phase A (32KB)
#define KTB    1024
#define CSPB   8                   // phase-B candidate split
#define CAP    1024                // survivor capacity per query

typedef unsigned long long u64;

#define PACK2(d, a) asm("mov.b64 %0, {%1, %2};" : "=l"(d) : "r"(__float_as_uint(a)), "r"(__float_as_uint(a)))
#define FMA2(d, a, b, c) asm("fma.rn.f32x2 %0, %1, %2, %3;" : "=l"(d) : "l"(a), "l"(b), "l"(c))
#define UNPACK2(lo, hi, in) asm("mov.b64 {%0, %1}, %2;" : "=r"(lo), "=r"(hi) : "l"(in))

// ---------------- scratch (no allocations allowed) ----------------
__device__ float4 g_c4[NMAX];
__device__ float  g_thr[NMAX];
__device__ int    g_scnt[NMAX];
__device__ int2   g_surv[(size_t)NMAX * CAP];   // (dist bits, idx)
__device__ int    g_idx[NMAX * KNN];
__device__ int    g_deg[NMAX];
__device__ float  g_srcnorm[NMAX];
__device__ float  g_bufA[NMAX * HDIM];
__device__ float  g_bufB[NMAX * HDIM];
__device__ float  g_bufC[NMAX * HDIM];

__device__ __forceinline__ float* bufptr(int s) {
    return s == 0 ? g_bufA : (s == 1 ? g_bufB : g_bufC);
}

// ---------------- pack centers into float4 (x,y,z,|c|^2), zero degrees/counters --------
__global__ void pack_kernel(const float* __restrict__ centers, int N) {
    int i = blockIdx.x * blockDim.x + threadIdx.x;
    if (i < N) {
        float x = centers[3 * i + 0];
        float y = centers[3 * i + 1];
        float z = centers[3 * i + 2];
        g_c4[i] = make_float4(x, y, z, x * x + y * y + z * z);
        g_deg[i] = 0;
        g_scnt[i] = 0;
    }
}

// ---------------- Phase A: threshold = 16th smallest of 512 sub-minima over 8192 sample --
// Sub-blocks are disjoint -> the 16 smallest sub-minima are 16 distinct candidates all <= t,
// hence t >= true 16th-NN distance: phase-B filter keeps a guaranteed superset of top-16.
__global__ void knn_thresh_kernel(int N) {
    __shared__ float4 sc[THTILE];
    int q = blockIdx.x * blockDim.x + threadIdx.x;
    float nx = 0.f, ny = 0.f, nz = 0.f;
    if (q < N) {
        float4 p = g_c4[q];
        nx = -2.f * p.x; ny = -2.f * p.y; nz = -2.f * p.z;
    }
    float bd[KNN];
#pragma unroll
    for (int k = 0; k < KNN; k++) bd[k] = 3.4e38f;

    int send = min(N, SAMPLE);
    for (int base = 0; base < send; base += THTILE) {
        int cnt = min(THTILE, send - base);
        __syncthreads();
        for (int t = threadIdx.x; t < cnt; t += blockDim.x) sc[t] = g_c4[base + t];
        __syncthreads();
        if (q < N) {
            int nsub = cnt / SUBW;       // ignore remainder (bound stays valid)
            for (int b = 0; b < nsub; b++) {
                float m0 = 3.4e38f, m1 = 3.4e38f;
#pragma unroll
                for (int j = 0; j < SUBW; j++) {
                    float4 v = sc[b * SUBW + j];
                    float d = fmaf(v.x, nx, fmaf(v.y, ny, fmaf(v.z, nz, v.w)));
                    if (j & 1) m1 = fminf(m1, d); else m0 = fminf(m0, d);
                }
                float cd = fminf(m0, m1);
                if (cd < bd[KNN - 1]) {
#pragma unroll
                    for (int k = 0; k < KNN; k++) {
                        float lo = fminf(cd, bd[k]);
                        float hi = fmaxf(cd, bd[k]);
                        bd[k] = lo; cd = hi;
                    }
                }
            }
        }
    }
    if (q < N) g_thr[q] = bd[KNN - 1];
}

// ---------------- Phase B: filtered full scan, append survivors ----------------
__global__ void knn_filter_kernel(int N) {
    __shared__ float4 sc[KTB];
    int half = (N + 1) >> 1;
    int t0i = blockIdx.x * blockDim.x + threadIdx.x;
    int q0 = t0i;
    int q1 = t0i + half;
    bool v0 = (q0 < N);
    bool v1 = (q1 < N);

    int chunk = (N + CSPB - 1) / CSPB;
    int c0 = blockIdx.y * chunk;
    int c1 = min(N, c0 + chunk);

    float nx0 = 0.f, ny0 = 0.f, nz0 = 0.f, th0 = -3.4e38f;
    float nx1 = 0.f, ny1 = 0.f, nz1 = 0.f, th1 = -3.4e38f;
    if (v0) {
        float4 p = g_c4[q0];
        nx0 = -2.f * p.x; ny0 = -2.f * p.y; nz0 = -2.f * p.z;
        th0 = g_thr[q0];
    }
    if (v1) {
        float4 p = g_c4[q1];
        nx1 = -2.f * p.x; ny1 = -2.f * p.y; nz1 = -2.f * p.z;
        th1 = g_thr[q1];
    }

    for (int base = c0; base < c1; base += KTB) {
        int cnt = min(KTB, c1 - base);
        __syncthreads();
        for (int t = threadIdx.x; t < cnt; t += blockDim.x) sc[t] = g_c4[base + t];
        __syncthreads();
#pragma unroll 4
        for (int t = 0; t < cnt; t++) {
            float4 v = sc[t];
            float d0 = fmaf(v.x, nx0, fmaf(v.y, ny0, fmaf(v.z, nz0, v.w)));
            float d1 = fmaf(v.x, nx1, fmaf(v.y, ny1, fmaf(v.z, nz1, v.w)));
            if (d0 <= th0) {
                int s = atomicAdd(&g_scnt[q0], 1);
                if (s < CAP) g_surv[(size_t)q0 * CAP + s] =
                    make_int2(__float_as_int(d0), base + t);
            }
            if (d1 <= th1) {
                int s = atomicAdd(&g_scnt[q1], 1);
                if (s < CAP) g_surv[(size_t)q1 * CAP + s] =
                    make_int2(__float_as_int(d1), base + t);
            }
        }
    }
}

// ---------------- Phase C: exact top-16 of survivors, 4 threads/query + 4-way merge ------
__global__ void knn_select_kernel(int N) {
    __shared__ float sd[32][4][KNN];
    __shared__ int   si[32][4][KNN];
    int tid = threadIdx.x;
    int sub = tid & 3;
    int qi  = tid >> 2;                 // 0..31
    int q = blockIdx.x * 32 + qi;
    bool valid = (q < N);

    float bd[KNN];
    int   bi[KNN];
#pragma unroll
    for (int k = 0; k < KNN; k++) { bd[k] = 3.4e38f; bi[k] = 0; }

    if (valid) {
        int cnt = min(g_scnt[q], CAP);
        const int2* sv = &g_surv[(size_t)q * CAP];
        for (int s = sub; s < cnt; s += 4) {
            int2 e = __ldg(&sv[s]);
            float cd = __int_as_float(e.x);
            if (cd < bd[KNN - 1]) {
                int ci = e.y;
#pragma unroll
                for (int k = 0; k < KNN; k++) {
                    bool lt = cd < bd[k];
                    float lo = fminf(cd, bd[k]);
                    float hi = fmaxf(cd, bd[k]);
                    int ni = lt ? ci : bi[k];
                    ci = lt ? bi[k] : ci;
                    bd[k] = lo; bi[k] = ni; cd = hi;
                }
            }
        }
    }
#pragma unroll
    for (int k = 0; k < KNN; k++) {
        sd[qi][sub][k] = bd[k];
        si[qi][sub][k] = bi[k];
    }
    __syncthreads();

    if (valid && sub == 0) {
        int p[4] = {0, 0, 0, 0};
#pragma unroll
        for (int k = 0; k < KNN; k++) {
            float best = 3.5e38f;
            int bl = 0;
#pragma unroll
            for (int l = 0; l < 4; l++) {
                float v = (p[l] < KNN) ? sd[qi][l][p[l]] : 3.5e38f;
                if (v < best) { best = v; bl = l; }
            }
            int j = si[qi][bl][p[bl]];
            p[bl]++;
            g_idx[q * KNN + k] = j;
            atomicAdd(&g_deg[j], 1);
        }
    }
}

// ---------------- src_norm = rsqrt(max(out_deg,1)) ----------------
__global__ void norm_kernel(int N) {
    int i = blockIdx.x * blockDim.x + threadIdx.x;
    if (i < N) {
        float d = (float)g_deg[i];
        g_srcnorm[i] = rsqrtf(fmaxf(d, 1.f));
    }
}

// ---------------- neighbor aggregation: agg[i] = 0.25 * sum_k srcnorm[j]*h[j] ----------
__global__ void agg_kernel(const float* __restrict__ xin, int srcSel, int dstSel,
                           int F, int N) {
    const float* src = (srcSel < 0) ? xin : bufptr(srcSel);
    float* dst = bufptr(dstSel);
    int tpr = F >> 2;
    int rpb = blockDim.x / tpr;
    int r = threadIdx.x / tpr;
    int c = threadIdx.x % tpr;
    int node = blockIdx.x * rpb + r;
    if (node >= N) return;
    const float4* s4 = (const float4*)src;
    float4 acc = make_float4(0.f, 0.f, 0.f, 0.f);
    const int* ip = &g_idx[node * KNN];
#pragma unroll
    for (int k = 0; k < KNN; k++) {
        int j = __ldg(&ip[k]);
        float s = __ldg(&g_srcnorm[j]);
        float4 v = s4[j * tpr + c];
        acc.x = fmaf(s, v.x, acc.x);
        acc.y = fmaf(s, v.y, acc.y);
        acc.z = fmaf(s, v.z, acc.z);
        acc.w = fmaf(s, v.w, acc.w);
    }
    const float dn = 0.25f;
    ((float4*)dst)[node * tpr + c] =
        make_float4(acc.x * dn, acc.y * dn, acc.z * dn, acc.w * dn);
}

// ---------------- fp32 tiled GEMM (packed f32x2 FFMA) + bias + relu --------------------
// BM=128, BN=128, BK=16, 256 threads, 8x8 micro-tile as 8x4 f32x2 pairs
__global__ void gemm_kernel(int srcSel, const float* __restrict__ W,
                            const float* __restrict__ bias, int dstSel,
                            int M, int Kd) {
    const float* A = bufptr(srcSel);
    float* C = bufptr(dstSel);
    __shared__ float As[16][132];
    __shared__ float Bs[16][128];
    int tid = threadIdx.x;
    int tx = tid & 15;
    int ty = tid >> 4;
    int bm0 = blockIdx.x * 128;
    int bn0 = blockIdx.y * 128;

    u64 acc2[8][4];
#pragma unroll
    for (int i = 0; i < 8; i++)
#pragma unroll
        for (int j = 0; j < 4; j++) acc2[i][j] = 0ull;

    int ktiles = Kd >> 4;
    for (int kt = 0; kt < ktiles; kt++) {
#pragma unroll
        for (int l = 0; l < 2; l++) {
            int lin = tid + l * 256;
            int arow = lin >> 2;
            int kq = (lin & 3) << 2;
            int grow = bm0 + arow;
            float4 v = make_float4(0.f, 0.f, 0.f, 0.f);
            if (grow < M) v = *(const float4*)&A[grow * Kd + kt * 16 + kq];
            As[kq + 0][arow] = v.x;
            As[kq + 1][arow] = v.y;
            As[kq + 2][arow] = v.z;
            As[kq + 3][arow] = v.w;
        }
#pragma unroll
        for (int l = 0; l < 2; l++) {
            int lin = tid + l * 256;
            int brow = lin >> 5;
            int bc = (lin & 31) << 2;
            float4 v = *(const float4*)&W[(kt * 16 + brow) * HDIM + bn0 + bc];
            *(float4*)&Bs[brow][bc] = v;
        }
        __syncthreads();
#pragma unroll
        for (int kk = 0; kk < 16; kk++) {
            float4 a0 = *(const float4*)&As[kk][ty * 8];
            float4 a1 = *(const float4*)&As[kk][ty * 8 + 4];
            ulonglong2 bp01 = *(const ulonglong2*)&Bs[kk][tx * 8];     // pairs (b0,b1),(b2,b3)
            ulonglong2 bp23 = *(const ulonglong2*)&Bs[kk][tx * 8 + 4]; // pairs (b4,b5),(b6,b7)
            u64 bp[4] = {bp01.x, bp01.y, bp23.x, bp23.y};
            float a[8] = {a0.x, a0.y, a0.z, a0.w, a1.x, a1.y, a1.z, a1.w};
#pragma unroll
            for (int i = 0; i < 8; i++) {
                u64 aa;
                PACK2(aa, a[i]);
#pragma unroll
                for (int j = 0; j < 4; j++)
                    FMA2(acc2[i][j], aa, bp[j], acc2[i][j]);
            }
        }
        __syncthreads();
    }

    float bb[8];
#pragma unroll
    for (int j = 0; j < 8; j++) bb[j] = __ldg(&bias[bn0 + tx * 8 + j]);
#pragma unroll
    for (int i = 0; i < 8; i++) {
        int row = bm0 + ty * 8 + i;
        if (row < M) {
            float o[8];
#pragma unroll
            for (int j = 0; j < 4; j++) {
                unsigned int lo, hi;
                UNPACK2(lo, hi, acc2[i][j]);
                o[2 * j + 0] = fmaxf(__uint_as_float(lo) + bb[2 * j + 0], 0.f);
                o[2 * j + 1] = fmaxf(__uint_as_float(hi) + bb[2 * j + 1], 0.f);
            }
            *(float4*)&C[row * HDIM + bn0 + tx * 8 + 0] = make_float4(o[0], o[1], o[2], o[3]);
            *(float4*)&C[row * HDIM + bn0 + tx * 8 + 4] = make_float4(o[4], o[5], o[6], o[7]);
        }
    }
}

// ---------------- final: sigmoid(h @ Wf + bf), one warp per row ----------------
__global__ void final_kernel(int srcSel, const float* __restrict__ Wf,
                             const float* __restrict__ bf,
                             float* __restrict__ out, int N) {
    __shared__ float sw[HDIM];
    const float* h = bufptr(srcSel);
    for (int i = threadIdx.x; i < HDIM; i += blockDim.x) sw[i] = Wf[i];
    __syncthreads();
    int warp = threadIdx.x >> 5;
    int lane = threadIdx.x & 31;
    int row = blockIdx.x * 8 + warp;
    if (row >= N) return;
    const float4* h4 = (const float4*)&h[row * HDIM];
    float4 v0 = h4[lane * 2 + 0];
    float4 v1 = h4[lane * 2 + 1];
    float4 w0 = *(const float4*)&sw[lane * 8 + 0];
    float4 w1 = *(const float4*)&sw[lane * 8 + 4];
    float s = v0.x * w0.x + v0.y * w0.y + v0.z * w0.z + v0.w * w0.w
            + v1.x * w1.x + v1.y * w1.y + v1.z * w1.z + v1.w * w1.w;
#pragma unroll
    for (int o = 16; o > 0; o >>= 1) s += __shfl_xor_sync(0xffffffffu, s, o);
    if (lane == 0) {
        float z = s + bf[0];
        out[row] = 1.f / (1.f + expf(-z));
    }
}

// ---------------- launch ----------------
extern "C" void kernel_launch(void* const* d_in, const int* in_sizes, int n_in,
                              void* d_out, int out_size) {
    const float* x       = (const float*)d_in[0];
    const float* centers = (const float*)d_in[1];
    const float* W0      = (const float*)d_in[2];
    const float* b0      = (const float*)d_in[3];
    const float* W1      = (const float*)d_in[4];
    const float* b1      = (const float*)d_in[5];
    const float* W2      = (const float*)d_in[6];
    const float* b2      = (const float*)d_in[7];
    const float* Wf      = (const float*)d_in[8];
    const float* bf      = (const float*)d_in[9];
    float* out = (float*)d_out;

    int N = in_sizes[1] / 3;           // 20000
    int D = in_sizes[0] / N;           // 128

    pack_kernel<<<(N + 255) / 256, 256>>>(centers, N);
    knn_thresh_kernel<<<(N + 127) / 128, 128>>>(N);
    {
        int half = (N + 1) / 2;
        dim3 kg((half + 127) / 128, CSPB);
        knn_filter_kernel<<<kg, 128>>>(N);
    }
    knn_select_kernel<<<(N + 31) / 32, 128>>>(N);
    norm_kernel<<<(N + 255) / 256, 256>>>(N);

    dim3 gg((N + 127) / 128, HDIM / 128);

    {
        int tpr = D / 4, rpb = 256 / tpr;
        agg_kernel<<<(N + rpb - 1) / rpb, 256>>>(x, -1, 0, D, N);
    }
    gemm_kernel<<<gg, 256>>>(0, W0, b0, 1, N, D);

    {
        int tpr = HDIM / 4, rpb = 256 / tpr;
        agg_kernel<<<(N + rpb - 1) / rpb, 256>>>(nullptr, 1, 0, HDIM, N);
    }
    gemm_kernel<<<gg, 256>>>(0, W1, b1, 2, N, HDIM);

    {
        int tpr = HDIM / 4, rpb = 256 / tpr;
        agg_kernel<<<(N + rpb - 1) / rpb, 256>>>(nullptr, 2, 0, HDIM, N);
    }
    gemm_kernel<<<gg, 256>>>(0, W2, b2, 1, N, HDIM);

    final_kernel<<<(N + 7) / 8, 256>>>(1, Wf, bf, out, N);
}